// round 1
// baseline (speedup 1.0000x reference)
#include <cuda_runtime.h>
#include <math.h>

#define D      13
#define DP     14          // padded feature dim (float2-aligned rows, 56B)
#define NPIX   1024
#define BATCH  32
#define TSTEPS 24
#define NCL    8

// ---------------- persistent state (device globals; no allocation) ----------------
__device__ float g_c   [BATCH*D*NPIX];
__device__ float g_h   [BATCH*D*NPIX];
__device__ float g_m   [BATCH*D*NPIX];
__device__ float g_htmp[BATCH*D*NPIX];
__device__ float g_q   [BATCH*NPIX*DP];
__device__ float g_kh  [BATCH*NPIX*DP];
__device__ float g_vh  [BATCH*NPIX*DP];
__device__ float g_km  [BATCH*NPIX*DP];
__device__ float g_vm  [BATCH*NPIX*DP];
__device__ float g_zh  [BATCH*D*NPIX];
__device__ float g_zm  [BATCH*D*NPIX];

// ---------------- zero init of recurrent state ----------------
__global__ void zero_state() {
    int total = BATCH*D*NPIX;
    for (int i = blockIdx.x*blockDim.x + threadIdx.x; i < total; i += gridDim.x*blockDim.x) {
        g_c[i] = 0.f; g_h[i] = 0.f; g_m[i] = 0.f;
    }
}

// ---------------- ConvLSTM: 3x3 conv on [x_t ; h] (26ch -> 52ch) fused with gate elementwise ----------------
#define CONV_W_FLOATS (52*26*9)        // 12168
#define CONV_TILE_FLOATS (26*10*34)    // 8840 (8-row tile + 1 halo each side, 34 cols)
#define CONV_SMEM ((CONV_W_FLOATS + CONV_TILE_FLOATS)*4)

__global__ void __launch_bounds__(256) conv_lstm_step(
        const float* __restrict__ x1, const float* __restrict__ Wg, int t) {
    extern __shared__ float sm[];
    float* sw = sm;                    // weights [52][26][3][3]
    float* st = sm + CONV_W_FLOATS;    // input tile [26][10][34]

    int b  = blockIdx.y;
    int y0 = blockIdx.x * 8;

    for (int i = threadIdx.x; i < CONV_W_FLOATS; i += 256) sw[i] = Wg[i];
    for (int i = threadIdx.x; i < CONV_TILE_FLOATS; i += 256) {
        int ci = i / 340; int rem = i % 340; int r = rem / 34; int cc = rem % 34;
        int y = y0 + r - 1, x = cc - 1;
        float v = 0.f;
        if ((unsigned)y < 32u && (unsigned)x < 32u) {
            int n = y*32 + x;
            v = (ci < 13) ? x1[(((size_t)b*TSTEPS + t)*D + ci)*NPIX + n]
                          : g_h[((size_t)b*D + (ci-13))*NPIX + n];
        }
        st[i] = v;
    }
    __syncthreads();

    int ly = threadIdx.x >> 5;   // 0..7
    int lx = threadIdx.x & 31;   // 0..31
    int n  = (y0 + ly)*32 + lx;

    for (int d = 0; d < D; d++) {
        const float* w_i = sw + (size_t)(     d)*234;
        const float* w_f = sw + (size_t)(13 + d)*234;
        const float* w_g = sw + (size_t)(26 + d)*234;
        const float* w_o = sw + (size_t)(39 + d)*234;
        float ai = 0.f, af = 0.f, ag = 0.f, ao = 0.f;
        for (int ci = 0; ci < 26; ci++) {
            const float* tb = st + (ci*10 + ly)*34 + lx;
            #pragma unroll
            for (int ky = 0; ky < 3; ky++) {
                const float* tr = tb + ky*34;
                #pragma unroll
                for (int kx = 0; kx < 3; kx++) {
                    float v = tr[kx];
                    int wi = ci*9 + ky*3 + kx;
                    ai = fmaf(w_i[wi], v, ai);
                    af = fmaf(w_f[wi], v, af);
                    ag = fmaf(w_g[wi], v, ag);
                    ao = fmaf(w_o[wi], v, ao);
                }
            }
        }
        float ig = 1.f/(1.f + __expf(-ai));
        float fg = 1.f/(1.f + __expf(-af));
        float og = 1.f/(1.f + __expf(-ao));
        float gg = tanhf(ag);
        size_t idx = ((size_t)b*D + d)*NPIX + n;
        float cn = fg*g_c[idx] + ig*gg;
        g_c[idx]    = cn;
        g_htmp[idx] = og*tanhf(cn);
    }
}

// ---------------- SAM projections: q,kh,vh from h_tmp; km,vm from m ----------------
__global__ void __launch_bounds__(256) sam_proj(
        const float* __restrict__ Wq,  const float* __restrict__ Wkh,
        const float* __restrict__ Wvh, const float* __restrict__ Wkm,
        const float* __restrict__ Wvm) {
    __shared__ float s[5*169];
    for (int i = threadIdx.x; i < 169; i += 256) {
        s[i]       = Wq[i];  s[169+i] = Wkh[i]; s[338+i] = Wvh[i];
        s[507+i]   = Wkm[i]; s[676+i] = Wvm[i];
    }
    __syncthreads();
    int g = blockIdx.x*256 + threadIdx.x;
    int b = g >> 10, n = g & 1023;
    float hv[D], mv[D];
    #pragma unroll
    for (int d = 0; d < D; d++) {
        hv[d] = g_htmp[((size_t)b*D + d)*NPIX + n];
        mv[d] = g_m   [((size_t)b*D + d)*NPIX + n];
    }
    size_t ob = ((size_t)b*NPIX + n)*DP;
    #pragma unroll
    for (int o = 0; o < D; o++) {
        float q = 0.f, kh = 0.f, vh = 0.f, km = 0.f, vm = 0.f;
        #pragma unroll
        for (int d = 0; d < D; d++) {
            q  = fmaf(s[      o*13 + d], hv[d], q);
            kh = fmaf(s[169 + o*13 + d], hv[d], kh);
            vh = fmaf(s[338 + o*13 + d], hv[d], vh);
            km = fmaf(s[507 + o*13 + d], mv[d], km);
            vm = fmaf(s[676 + o*13 + d], mv[d], vm);
        }
        g_q[ob+o] = q; g_kh[ob+o] = kh; g_vh[ob+o] = vh;
        g_km[ob+o] = km; g_vm[ob+o] = vm;
    }
    g_q[ob+13] = 0.f; g_kh[ob+13] = 0.f; g_vh[ob+13] = 0.f;
    g_km[ob+13] = 0.f; g_vm[ob+13] = 0.f;
}

// ---------------- fused double attention (Zh and Zm share q), flash-style online softmax ----------------
#define ATTN_SMEM (4*DP*NPIX*4)   // 229376 bytes

__global__ void __launch_bounds__(256) sam_attn() {
    extern __shared__ float sm[];
    float* skh = sm;
    float* svh = sm +   DP*NPIX;
    float* skm = sm + 2*DP*NPIX;
    float* svm = sm + 3*DP*NPIX;

    int b = blockIdx.y;
    size_t base = (size_t)b*NPIX*DP;
    for (int i = threadIdx.x; i < DP*NPIX; i += 256) {
        skh[i] = g_kh[base+i]; svh[i] = g_vh[base+i];
        skm[i] = g_km[base+i]; svm[i] = g_vm[base+i];
    }
    __syncthreads();

    int n = blockIdx.x*256 + threadIdx.x;
    float qv[D];
    #pragma unroll
    for (int d = 0; d < D; d++) qv[d] = g_q[base + (size_t)n*DP + d];

    float aH[D], aM[D];
    #pragma unroll
    for (int d = 0; d < D; d++) { aH[d] = 0.f; aM[d] = 0.f; }
    float mH = -INFINITY, sH = 0.f;
    float mM = -INFINITY, sM = 0.f;

    for (int j = 0; j < NPIX; j++) {
        const float2* k2h = (const float2*)(skh + j*DP);   // 56B rows -> 8B aligned
        const float2* k2m = (const float2*)(skm + j*DP);
        float sa = 0.f, sb = 0.f, ta = 0.f, tb = 0.f;
        #pragma unroll
        for (int p = 0; p < 6; p++) {
            float2 kh2 = k2h[p], km2 = k2m[p];
            sa = fmaf(qv[2*p],   kh2.x, sa);
            sb = fmaf(qv[2*p+1], kh2.y, sb);
            ta = fmaf(qv[2*p],   km2.x, ta);
            tb = fmaf(qv[2*p+1], km2.y, tb);
        }
        float scH = fmaf(qv[12], skh[j*DP+12], sa) + sb;
        float scM = fmaf(qv[12], skm[j*DP+12], ta) + tb;

        const float* vh = svh + j*DP;
        const float* vm = svm + j*DP;

        if (scH <= mH) {
            float p = __expf(scH - mH);
            sH += p;
            #pragma unroll
            for (int d = 0; d < D; d++) aH[d] = fmaf(p, vh[d], aH[d]);
        } else {
            float r = __expf(mH - scH);        // first iter: exp(-inf)=0
            sH = fmaf(sH, r, 1.f);
            #pragma unroll
            for (int d = 0; d < D; d++) aH[d] = fmaf(aH[d], r, vh[d]);
            mH = scH;
        }
        if (scM <= mM) {
            float p = __expf(scM - mM);
            sM += p;
            #pragma unroll
            for (int d = 0; d < D; d++) aM[d] = fmaf(p, vm[d], aM[d]);
        } else {
            float r = __expf(mM - scM);
            sM = fmaf(sM, r, 1.f);
            #pragma unroll
            for (int d = 0; d < D; d++) aM[d] = fmaf(aM[d], r, vm[d]);
            mM = scM;
        }
    }
    float invH = 1.f/sH, invM = 1.f/sM;
    #pragma unroll
    for (int d = 0; d < D; d++) {
        g_zh[((size_t)b*D + d)*NPIX + n] = aH[d]*invH;
        g_zm[((size_t)b*D + d)*NPIX + n] = aM[d]*invM;
    }
}

// ---------------- SAM fuse: Z = Wz[Zh;Zm]; comb = Wm[Z;h]; memory/hidden update ----------------
__global__ void __launch_bounds__(256) sam_post(
        const float* __restrict__ Wz, const float* __restrict__ Wm) {
    __shared__ float swz[13*26], swm[39*26];
    for (int i = threadIdx.x; i < 13*26; i += 256) swz[i] = Wz[i];
    for (int i = threadIdx.x; i < 39*26; i += 256) swm[i] = Wm[i];
    __syncthreads();
    int g = blockIdx.x*256 + threadIdx.x;
    int b = g >> 10, n = g & 1023;
    float zh[D], zm[D], hf[D], mf[D];
    #pragma unroll
    for (int d = 0; d < D; d++) {
        size_t idx = ((size_t)b*D + d)*NPIX + n;
        zh[d] = g_zh[idx]; zm[d] = g_zm[idx];
        hf[d] = g_htmp[idx]; mf[d] = g_m[idx];
    }
    float Z[D];
    #pragma unroll
    for (int o = 0; o < D; o++) {
        float a = 0.f;
        #pragma unroll
        for (int c = 0; c < D; c++) {
            a = fmaf(swz[o*26 + c],      zh[c], a);
            a = fmaf(swz[o*26 + 13 + c], zm[c], a);
        }
        Z[o] = a;
    }
    #pragma unroll
    for (int o = 0; o < D; o++) {
        float ao = 0.f, ag = 0.f, ai = 0.f;
        #pragma unroll
        for (int c = 0; c < D; c++) {
            ao = fmaf(swm[(     o)*26 + c], Z[c], ao); ao = fmaf(swm[(     o)*26 + 13 + c], hf[c], ao);
            ag = fmaf(swm[(13 + o)*26 + c], Z[c], ag); ag = fmaf(swm[(13 + o)*26 + 13 + c], hf[c], ag);
            ai = fmaf(swm[(26 + o)*26 + c], Z[c], ai); ai = fmaf(swm[(26 + o)*26 + 13 + c], hf[c], ai);
        }
        float mi = 1.f/(1.f + __expf(-ai));
        float mn = (1.f - mi)*mf[o] + mi*tanhf(ag);
        size_t idx = ((size_t)b*D + o)*NPIX + n;
        g_m[idx] = mn;
        g_h[idx] = mn/(1.f + __expf(-ao));
    }
}

// ---------------- final 1x1 conv (13->8) + bias + log_softmax over channels ----------------
__global__ void __launch_bounds__(256) final_logsoftmax(
        const float* __restrict__ Wf, const float* __restrict__ bf,
        float* __restrict__ out) {
    __shared__ float sw[NCL*D], sb[NCL];
    for (int i = threadIdx.x; i < NCL*D; i += 256) sw[i] = Wf[i];
    if (threadIdx.x < NCL) sb[threadIdx.x] = bf[threadIdx.x];
    __syncthreads();
    int g = blockIdx.x*256 + threadIdx.x;
    int b = g >> 10, n = g & 1023;
    float cv[D];
    #pragma unroll
    for (int d = 0; d < D; d++) cv[d] = g_c[((size_t)b*D + d)*NPIX + n];
    float l[NCL]; float mx = -INFINITY;
    #pragma unroll
    for (int o = 0; o < NCL; o++) {
        float a = sb[o];
        #pragma unroll
        for (int d = 0; d < D; d++) a = fmaf(sw[o*13 + d], cv[d], a);
        l[o] = a; mx = fmaxf(mx, a);
    }
    float sum = 0.f;
    #pragma unroll
    for (int o = 0; o < NCL; o++) sum += __expf(l[o] - mx);
    float lse = mx + logf(sum);
    #pragma unroll
    for (int o = 0; o < NCL; o++)
        out[((size_t)b*NCL + o)*NPIX + n] = l[o] - lse;
}

// ---------------- launch ----------------
extern "C" void kernel_launch(void* const* d_in, const int* in_sizes, int n_in,
                              void* d_out, int out_size) {
    const float* x1  = (const float*)d_in[0];
    const float* Wg  = (const float*)d_in[1];
    const float* Wq  = (const float*)d_in[2];
    const float* Wkh = (const float*)d_in[3];
    const float* Wvh = (const float*)d_in[4];
    const float* Wkm = (const float*)d_in[5];
    const float* Wvm = (const float*)d_in[6];
    const float* Wz  = (const float*)d_in[7];
    const float* Wm  = (const float*)d_in[8];
    const float* Wf  = (const float*)d_in[9];
    const float* bf  = (const float*)d_in[10];
    float* out = (float*)d_out;

    cudaFuncSetAttribute(sam_attn, cudaFuncAttributeMaxDynamicSharedMemorySize, ATTN_SMEM);
    cudaFuncSetAttribute(conv_lstm_step, cudaFuncAttributeMaxDynamicSharedMemorySize, CONV_SMEM);

    zero_state<<<256, 256>>>();
    for (int t = 0; t < TSTEPS; t++) {
        conv_lstm_step<<<dim3(4, BATCH), 256, CONV_SMEM>>>(x1, Wg, t);
        sam_proj<<<128, 256>>>(Wq, Wkh, Wvh, Wkm, Wvm);
        sam_attn<<<dim3(4, BATCH), 256, ATTN_SMEM>>>();
        sam_post<<<128, 256>>>(Wz, Wm);
    }
    final_logsoftmax<<<128, 256>>>(Wf, bf, out);
}

// round 2
// speedup vs baseline: 1.8794x; 1.8794x over previous
#include <cuda_runtime.h>
#include <math.h>

#define D      13
#define NPIX   1024
#define BATCH  32
#define TSTEPS 24
#define NCL    8
#define KHALF  512

typedef unsigned long long u64;

__device__ __forceinline__ u64 fma2(u64 a, u64 b, u64 c) {
    u64 d; asm("fma.rn.f32x2 %0, %1, %2, %3;" : "=l"(d) : "l"(a), "l"(b), "l"(c)); return d;
}
__device__ __forceinline__ u64 pack2(float lo, float hi) {
    u64 d; asm("mov.b64 %0, {%1, %2};" : "=l"(d) : "f"(lo), "f"(hi)); return d;
}
__device__ __forceinline__ void unpack2(u64 v, float& lo, float& hi) {
    asm("mov.b64 {%0, %1}, %2;" : "=f"(lo), "=f"(hi) : "l"(v));
}

// ---------------- persistent state (device globals; no allocation) ----------------
__device__ float g_c   [BATCH*D*NPIX];
__device__ float g_h   [BATCH*D*NPIX];
__device__ float g_m   [BATCH*D*NPIX];
__device__ float g_htmp[BATCH*D*NPIX];
__device__ float g_qT  [BATCH*D*NPIX];          // [b][d][n]
__device__ u64   g_khd [BATCH*NPIX*D];          // duplicated (k,k) pairs, [b][n][d]
__device__ u64   g_vhd [BATCH*NPIX*D];
__device__ u64   g_kmd [BATCH*NPIX*D];
__device__ u64   g_vmd [BATCH*NPIX*D];
__device__ float g_part[2*BATCH*2*NPIX*14];     // [att][b][half][n][{a0..a12,s}]

__device__ __forceinline__ size_t part_idx(int att, int b, int half, int n) {
    return ((((size_t)att*BATCH + b)*2 + half)*NPIX + n)*14;
}

// ---------------- zero init of recurrent state ----------------
__global__ void zero_state() {
    int total = BATCH*D*NPIX;
    for (int i = blockIdx.x*blockDim.x + threadIdx.x; i < total; i += gridDim.x*blockDim.x) {
        g_c[i] = 0.f; g_h[i] = 0.f; g_m[i] = 0.f;
    }
}

// ---------------- ConvLSTM: 3x3 conv on [x_t ; h] fused with gate elementwise ----------------
#define CONV_WP      (13*26*9)          // 3042 u64 per packed array
#define CONV_TILE_F  (26*10*34)         // 8840 floats
#define CONV_SMEM2   (2*CONV_WP*8 + CONV_TILE_F*4)   // 84032 B

__global__ void __launch_bounds__(256) conv_lstm_step(
        const float* __restrict__ x1, const float* __restrict__ Wg, int t) {
    extern __shared__ char smraw[];
    u64*   swif = (u64*)smraw;                 // (w_i, w_f) pairs, [d][ci*9+k]
    u64*   swgo = swif + CONV_WP;              // (w_g, w_o) pairs
    float* st   = (float*)(swgo + CONV_WP);    // input tile [26][10][34]

    int b  = blockIdx.y;
    int y0 = blockIdx.x * 8;

    for (int i = threadIdx.x; i < CONV_WP; i += 256) {
        int d = i / 234, r = i % 234;
        swif[i] = pack2(Wg[(     d)*234 + r], Wg[(13 + d)*234 + r]);
        swgo[i] = pack2(Wg[(26 + d)*234 + r], Wg[(39 + d)*234 + r]);
    }
    for (int i = threadIdx.x; i < CONV_TILE_F; i += 256) {
        int ci = i / 340; int rem = i % 340; int r = rem / 34; int cc = rem % 34;
        int y = y0 + r - 1, x = cc - 1;
        float v = 0.f;
        if ((unsigned)y < 32u && (unsigned)x < 32u) {
            int n = y*32 + x;
            v = (ci < 13) ? x1[(((size_t)b*TSTEPS + t)*D + ci)*NPIX + n]
                          : g_h[((size_t)b*D + (ci-13))*NPIX + n];
        }
        st[i] = v;
    }
    __syncthreads();

    int ly = threadIdx.x >> 5;
    int lx = threadIdx.x & 31;
    int n  = (y0 + ly)*32 + lx;

    u64 aif[D], ago[D];
    #pragma unroll
    for (int d = 0; d < D; d++) { aif[d] = 0ull; ago[d] = 0ull; }

    for (int ci = 0; ci < 26; ci++) {
        const float* tb = st + (ci*10 + ly)*34 + lx;
        #pragma unroll
        for (int ky = 0; ky < 3; ky++) {
            #pragma unroll
            for (int kx = 0; kx < 3; kx++) {
                float v = tb[ky*34 + kx];
                u64 vv = pack2(v, v);
                int r = ci*9 + ky*3 + kx;
                #pragma unroll
                for (int d = 0; d < D; d++) {
                    aif[d] = fma2(swif[d*234 + r], vv, aif[d]);
                    ago[d] = fma2(swgo[d*234 + r], vv, ago[d]);
                }
            }
        }
    }

    #pragma unroll
    for (int d = 0; d < D; d++) {
        float ai, af, ag, ao;
        unpack2(aif[d], ai, af);
        unpack2(ago[d], ag, ao);
        float ig = 1.f/(1.f + __expf(-ai));
        float fg = 1.f/(1.f + __expf(-af));
        float og = 1.f/(1.f + __expf(-ao));
        float gg = tanhf(ag);
        size_t idx = ((size_t)b*D + d)*NPIX + n;
        float cn = fg*g_c[idx] + ig*gg;
        g_c[idx]    = cn;
        g_htmp[idx] = og*tanhf(cn);
    }
}

// ---------------- SAM projections: q,kh,vh from h_tmp; km,vm from m ----------------
__global__ void __launch_bounds__(256) sam_proj(
        const float* __restrict__ Wq,  const float* __restrict__ Wkh,
        const float* __restrict__ Wvh, const float* __restrict__ Wkm,
        const float* __restrict__ Wvm) {
    __shared__ float s[5*169];
    for (int i = threadIdx.x; i < 169; i += 256) {
        s[i]     = Wq[i];  s[169+i] = Wkh[i]; s[338+i] = Wvh[i];
        s[507+i] = Wkm[i]; s[676+i] = Wvm[i];
    }
    __syncthreads();
    int g = blockIdx.x*256 + threadIdx.x;
    int b = g >> 10, n = g & 1023;
    float hv[D], mv[D];
    #pragma unroll
    for (int d = 0; d < D; d++) {
        hv[d] = g_htmp[((size_t)b*D + d)*NPIX + n];
        mv[d] = g_m   [((size_t)b*D + d)*NPIX + n];
    }
    size_t kb = ((size_t)b*NPIX + n)*D;
    #pragma unroll
    for (int o = 0; o < D; o++) {
        float q = 0.f, kh = 0.f, vh = 0.f, km = 0.f, vm = 0.f;
        #pragma unroll
        for (int d = 0; d < D; d++) {
            q  = fmaf(s[      o*13 + d], hv[d], q);
            kh = fmaf(s[169 + o*13 + d], hv[d], kh);
            vh = fmaf(s[338 + o*13 + d], hv[d], vh);
            km = fmaf(s[507 + o*13 + d], mv[d], km);
            vm = fmaf(s[676 + o*13 + d], mv[d], vm);
        }
        g_qT[((size_t)b*D + o)*NPIX + n] = q;
        g_khd[kb+o] = pack2(kh, kh);
        g_vhd[kb+o] = pack2(vh, vh);
        g_kmd[kb+o] = pack2(km, km);
        g_vmd[kb+o] = pack2(vm, vm);
    }
}

// ---------------- attention: split-K, no-max softmax, f32x2 packed (2 queries/thread) ----------------
#define ATTN2_SMEM (2*KHALF*D*8)   // 106496 B

__global__ void __launch_bounds__(512) sam_attn2() {
    extern __shared__ u64 sm64[];
    u64* sk = sm64;             // [512][13] duplicated key pairs
    u64* sv = sm64 + KHALF*D;   // [512][13] duplicated value pairs

    int half = blockIdx.x;      // key half
    int b    = blockIdx.y;
    int att  = blockIdx.z;      // 0 = H, 1 = M

    const u64* Kd = (att ? g_kmd : g_khd) + ((size_t)b*NPIX + (size_t)half*KHALF)*D;
    const u64* Vd = (att ? g_vmd : g_vhd) + ((size_t)b*NPIX + (size_t)half*KHALF)*D;
    for (int i = threadIdx.x; i < KHALF*D; i += 512) { sk[i] = Kd[i]; sv[i] = Vd[i]; }
    __syncthreads();

    // two queries per thread: tid and tid+512
    const float* qb = g_qT + (size_t)b*D*NPIX;
    int q0 = threadIdx.x, q1 = threadIdx.x + 512;
    u64 q2[D];
    #pragma unroll
    for (int d = 0; d < D; d++) q2[d] = pack2(qb[d*NPIX + q0], qb[d*NPIX + q1]);

    u64 acc[D];
    #pragma unroll
    for (int d = 0; d < D; d++) acc[d] = 0ull;
    float s0 = 0.f, s1 = 0.f;

    #pragma unroll 2
    for (int j = 0; j < KHALF; j++) {
        const u64* kr = sk + j*D;
        // two partial chains for ILP
        u64 sa = 0ull, sb = 0ull;
        #pragma unroll
        for (int d = 0; d < 12; d += 2) {
            sa = fma2(q2[d],   kr[d],   sa);
            sb = fma2(q2[d+1], kr[d+1], sb);
        }
        sa = fma2(q2[12], kr[12], sa);
        float scA0, scA1, scB0, scB1;
        unpack2(sa, scA0, scA1);
        unpack2(sb, scB0, scB1);
        float p0 = __expf(scA0 + scB0);
        float p1 = __expf(scA1 + scB1);
        s0 += p0; s1 += p1;
        u64 p2 = pack2(p0, p1);
        const u64* vr = sv + j*D;
        #pragma unroll
        for (int d = 0; d < D; d++) acc[d] = fma2(p2, vr[d], acc[d]);
    }

    float* o0 = g_part + part_idx(att, b, half, q0);
    float* o1 = g_part + part_idx(att, b, half, q1);
    #pragma unroll
    for (int d = 0; d < D; d++) {
        float lo, hi; unpack2(acc[d], lo, hi);
        o0[d] = lo; o1[d] = hi;
    }
    o0[13] = s0; o1[13] = s1;
}

// ---------------- SAM fuse (reads attention partials): Z = Wz[Zh;Zm]; comb = Wm[Z;h]; update ----------------
__global__ void __launch_bounds__(256) sam_post(
        const float* __restrict__ Wz, const float* __restrict__ Wm) {
    __shared__ float swz[13*26], swm[39*26];
    for (int i = threadIdx.x; i < 13*26; i += 256) swz[i] = Wz[i];
    for (int i = threadIdx.x; i < 39*26; i += 256) swm[i] = Wm[i];
    __syncthreads();
    int g = blockIdx.x*256 + threadIdx.x;
    int b = g >> 10, n = g & 1023;

    const float* h0 = g_part + part_idx(0, b, 0, n);
    const float* h1 = g_part + part_idx(0, b, 1, n);
    const float* m0 = g_part + part_idx(1, b, 0, n);
    const float* m1 = g_part + part_idx(1, b, 1, n);
    float invH = 1.f/(h0[13] + h1[13]);
    float invM = 1.f/(m0[13] + m1[13]);

    float zh[D], zm[D], hf[D], mf[D];
    #pragma unroll
    for (int d = 0; d < D; d++) {
        zh[d] = (h0[d] + h1[d])*invH;
        zm[d] = (m0[d] + m1[d])*invM;
        size_t idx = ((size_t)b*D + d)*NPIX + n;
        hf[d] = g_htmp[idx]; mf[d] = g_m[idx];
    }
    float Z[D];
    #pragma unroll
    for (int o = 0; o < D; o++) {
        float a = 0.f;
        #pragma unroll
        for (int c = 0; c < D; c++) {
            a = fmaf(swz[o*26 + c],      zh[c], a);
            a = fmaf(swz[o*26 + 13 + c], zm[c], a);
        }
        Z[o] = a;
    }
    #pragma unroll
    for (int o = 0; o < D; o++) {
        float ao = 0.f, ag = 0.f, ai = 0.f;
        #pragma unroll
        for (int c = 0; c < D; c++) {
            ao = fmaf(swm[(     o)*26 + c], Z[c], ao); ao = fmaf(swm[(     o)*26 + 13 + c], hf[c], ao);
            ag = fmaf(swm[(13 + o)*26 + c], Z[c], ag); ag = fmaf(swm[(13 + o)*26 + 13 + c], hf[c], ag);
            ai = fmaf(swm[(26 + o)*26 + c], Z[c], ai); ai = fmaf(swm[(26 + o)*26 + 13 + c], hf[c], ai);
        }
        float mi = 1.f/(1.f + __expf(-ai));
        float mn = (1.f - mi)*mf[o] + mi*tanhf(ag);
        size_t idx = ((size_t)b*D + o)*NPIX + n;
        g_m[idx] = mn;
        g_h[idx] = mn/(1.f + __expf(-ao));
    }
}

// ---------------- final 1x1 conv (13->8) + bias + log_softmax over channels ----------------
__global__ void __launch_bounds__(256) final_logsoftmax(
        const float* __restrict__ Wf, const float* __restrict__ bf,
        float* __restrict__ out) {
    __shared__ float sw[NCL*D], sb[NCL];
    for (int i = threadIdx.x; i < NCL*D; i += 256) sw[i] = Wf[i];
    if (threadIdx.x < NCL) sb[threadIdx.x] = bf[threadIdx.x];
    __syncthreads();
    int g = blockIdx.x*256 + threadIdx.x;
    int b = g >> 10, n = g & 1023;
    float cv[D];
    #pragma unroll
    for (int d = 0; d < D; d++) cv[d] = g_c[((size_t)b*D + d)*NPIX + n];
    float l[NCL]; float mx = -INFINITY;
    #pragma unroll
    for (int o = 0; o < NCL; o++) {
        float a = sb[o];
        #pragma unroll
        for (int d = 0; d < D; d++) a = fmaf(sw[o*13 + d], cv[d], a);
        l[o] = a; mx = fmaxf(mx, a);
    }
    float sum = 0.f;
    #pragma unroll
    for (int o = 0; o < NCL; o++) sum += __expf(l[o] - mx);
    float lse = mx + logf(sum);
    #pragma unroll
    for (int o = 0; o < NCL; o++)
        out[((size_t)b*NCL + o)*NPIX + n] = l[o] - lse;
}

// ---------------- launch ----------------
extern "C" void kernel_launch(void* const* d_in, const int* in_sizes, int n_in,
                              void* d_out, int out_size) {
    const float* x1  = (const float*)d_in[0];
    const float* Wg  = (const float*)d_in[1];
    const float* Wq  = (const float*)d_in[2];
    const float* Wkh = (const float*)d_in[3];
    const float* Wvh = (const float*)d_in[4];
    const float* Wkm = (const float*)d_in[5];
    const float* Wvm = (const float*)d_in[6];
    const float* Wz  = (const float*)d_in[7];
    const float* Wm  = (const float*)d_in[8];
    const float* Wf  = (const float*)d_in[9];
    const float* bf  = (const float*)d_in[10];
    float* out = (float*)d_out;

    cudaFuncSetAttribute(sam_attn2, cudaFuncAttributeMaxDynamicSharedMemorySize, ATTN2_SMEM);
    cudaFuncSetAttribute(conv_lstm_step, cudaFuncAttributeMaxDynamicSharedMemorySize, CONV_SMEM2);

    zero_state<<<256, 256>>>();
    for (int t = 0; t < TSTEPS; t++) {
        conv_lstm_step<<<dim3(4, BATCH), 256, CONV_SMEM2>>>(x1, Wg, t);
        sam_proj<<<128, 256>>>(Wq, Wkh, Wvh, Wkm, Wvm);
        sam_attn2<<<dim3(2, BATCH, 2), 512, ATTN2_SMEM>>>();
        sam_post<<<128, 256>>>(Wz, Wm);
    }
    final_logsoftmax<<<128, 256>>>(Wf, bf, out);
}

// round 3
// speedup vs baseline: 1.9076x; 1.0150x over previous
#include <cuda_runtime.h>
#include <math.h>

#define D      13
#define DP     14          // padded row (u64 units) -> 112B, 16B aligned
#define NPIX   1024
#define BATCH  32
#define TSTEPS 24
#define NCL    8
#define KQ     256         // keys per attention block (4 splits)
#define NSPLIT 4

typedef unsigned long long u64;

__device__ __forceinline__ u64 fma2(u64 a, u64 b, u64 c) {
    u64 d; asm("fma.rn.f32x2 %0, %1, %2, %3;" : "=l"(d) : "l"(a), "l"(b), "l"(c)); return d;
}
__device__ __forceinline__ u64 add2(u64 a, u64 b) {
    u64 d; asm("add.rn.f32x2 %0, %1, %2;" : "=l"(d) : "l"(a), "l"(b)); return d;
}
__device__ __forceinline__ u64 pack2(float lo, float hi) {
    u64 d; asm("mov.b64 %0, {%1, %2};" : "=l"(d) : "f"(lo), "f"(hi)); return d;
}
__device__ __forceinline__ void unpack2(u64 v, float& lo, float& hi) {
    asm("mov.b64 {%0, %1}, %2;" : "=f"(lo), "=f"(hi) : "l"(v));
}
__device__ __forceinline__ float ex2f(float x) {
    float r; asm("ex2.approx.f32 %0, %1;" : "=f"(r) : "f"(x)); return r;
}

// ---------------- persistent state (device globals; no allocation) ----------------
__device__ float g_c   [BATCH*D*NPIX];
__device__ float g_h   [BATCH*D*NPIX];
__device__ float g_m   [BATCH*D*NPIX];
__device__ float g_htmp[BATCH*D*NPIX];
__device__ float g_qT  [BATCH*D*NPIX];          // [b][d][n]
__device__ u64   g_khd [BATCH*NPIX*DP];         // duplicated (k,k) pairs, padded rows
__device__ u64   g_vhd [BATCH*NPIX*DP];
__device__ u64   g_kmd [BATCH*NPIX*DP];
__device__ u64   g_vmd [BATCH*NPIX*DP];
__device__ float g_part[2*BATCH*NSPLIT*NPIX*14]; // [att][b][split][n][{a0..a12,s}]

__device__ __forceinline__ size_t part_idx(int att, int b, int sp, int n) {
    return ((((size_t)att*BATCH + b)*NSPLIT + sp)*NPIX + n)*14;
}

// ---------------- zero init ----------------
__global__ void zero_state() {
    int total = BATCH*D*NPIX;
    for (int i = blockIdx.x*blockDim.x + threadIdx.x; i < total; i += gridDim.x*blockDim.x) {
        g_c[i] = 0.f; g_h[i] = 0.f; g_m[i] = 0.f;
    }
}

// ---------------- conv weight pre-pack (once per launch) ----------------
#define CONV_WP (13*26*9)   // 3042 u64 per array
__device__ u64 g_wif[CONV_WP];
__device__ u64 g_wgo[CONV_WP];

__global__ void pack_conv_weights(const float* __restrict__ Wg) {
    int i = blockIdx.x*256 + threadIdx.x;
    if (i < CONV_WP) {
        int d = i / 234, r = i % 234;
        g_wif[i] = pack2(Wg[(     d)*234 + r], Wg[(13 + d)*234 + r]);
        g_wgo[i] = pack2(Wg[(26 + d)*234 + r], Wg[(39 + d)*234 + r]);
    }
}

// ---------------- ConvLSTM step ----------------
#define CONV_TILE_F  (26*10*34)
#define CONV_SMEM3   (2*CONV_WP*8 + CONV_TILE_F*4)

__global__ void __launch_bounds__(256) conv_lstm_step(
        const float* __restrict__ x1, int t) {
    extern __shared__ char smraw[];
    u64*   swif = (u64*)smraw;
    u64*   swgo = swif + CONV_WP;
    float* st   = (float*)(swgo + CONV_WP);

    int b  = blockIdx.y;
    int y0 = blockIdx.x * 8;

    const ulonglong2* gi = (const ulonglong2*)g_wif;
    const ulonglong2* go = (const ulonglong2*)g_wgo;
    ulonglong2* si = (ulonglong2*)swif;
    ulonglong2* so = (ulonglong2*)swgo;
    for (int i = threadIdx.x; i < CONV_WP/2; i += 256) { si[i] = gi[i]; so[i] = go[i]; }
    if (threadIdx.x == 0) { swif[CONV_WP-1] = g_wif[CONV_WP-1]; swgo[CONV_WP-1] = g_wgo[CONV_WP-1]; }
    for (int i = threadIdx.x; i < CONV_TILE_F; i += 256) {
        int ci = i / 340; int rem = i % 340; int r = rem / 34; int cc = rem % 34;
        int y = y0 + r - 1, x = cc - 1;
        float v = 0.f;
        if ((unsigned)y < 32u && (unsigned)x < 32u) {
            int n = y*32 + x;
            v = (ci < 13) ? x1[(((size_t)b*TSTEPS + t)*D + ci)*NPIX + n]
                          : g_h[((size_t)b*D + (ci-13))*NPIX + n];
        }
        st[i] = v;
    }
    __syncthreads();

    int ly = threadIdx.x >> 5;
    int lx = threadIdx.x & 31;
    int n  = (y0 + ly)*32 + lx;

    u64 aif[D], ago[D];
    #pragma unroll
    for (int d = 0; d < D; d++) { aif[d] = 0ull; ago[d] = 0ull; }

    for (int ci = 0; ci < 26; ci++) {
        const float* tb = st + (ci*10 + ly)*34 + lx;
        #pragma unroll
        for (int ky = 0; ky < 3; ky++) {
            #pragma unroll
            for (int kx = 0; kx < 3; kx++) {
                float v = tb[ky*34 + kx];
                u64 vv = pack2(v, v);
                int r = ci*9 + ky*3 + kx;
                #pragma unroll
                for (int d = 0; d < D; d++) {
                    aif[d] = fma2(swif[d*234 + r], vv, aif[d]);
                    ago[d] = fma2(swgo[d*234 + r], vv, ago[d]);
                }
            }
        }
    }

    #pragma unroll
    for (int d = 0; d < D; d++) {
        float ai, af, ag, ao;
        unpack2(aif[d], ai, af);
        unpack2(ago[d], ag, ao);
        float ig = 1.f/(1.f + __expf(-ai));
        float fg = 1.f/(1.f + __expf(-af));
        float og = 1.f/(1.f + __expf(-ao));
        float gg = tanhf(ag);
        size_t idx = ((size_t)b*D + d)*NPIX + n;
        float cn = fg*g_c[idx] + ig*gg;
        g_c[idx]    = cn;
        g_htmp[idx] = og*tanhf(cn);
    }
}

// ---------------- SAM projections ----------------
__global__ void __launch_bounds__(256) sam_proj(
        const float* __restrict__ Wq,  const float* __restrict__ Wkh,
        const float* __restrict__ Wvh, const float* __restrict__ Wkm,
        const float* __restrict__ Wvm) {
    __shared__ float s[5*169];
    for (int i = threadIdx.x; i < 169; i += 256) {
        s[i]     = Wq[i];  s[169+i] = Wkh[i]; s[338+i] = Wvh[i];
        s[507+i] = Wkm[i]; s[676+i] = Wvm[i];
    }
    __syncthreads();
    int g = blockIdx.x*256 + threadIdx.x;
    int b = g >> 10, n = g & 1023;
    float hv[D], mv[D];
    #pragma unroll
    for (int d = 0; d < D; d++) {
        hv[d] = g_htmp[((size_t)b*D + d)*NPIX + n];
        mv[d] = g_m   [((size_t)b*D + d)*NPIX + n];
    }
    size_t kb = ((size_t)b*NPIX + n)*DP;
    #pragma unroll
    for (int o = 0; o < D; o++) {
        float q = 0.f, kh = 0.f, vh = 0.f, km = 0.f, vm = 0.f;
        #pragma unroll
        for (int d = 0; d < D; d++) {
            q  = fmaf(s[      o*13 + d], hv[d], q);
            kh = fmaf(s[169 + o*13 + d], hv[d], kh);
            vh = fmaf(s[338 + o*13 + d], hv[d], vh);
            km = fmaf(s[507 + o*13 + d], mv[d], km);
            vm = fmaf(s[676 + o*13 + d], mv[d], vm);
        }
        g_qT[((size_t)b*D + o)*NPIX + n] = q;
        g_khd[kb+o] = pack2(kh, kh);
        g_vhd[kb+o] = pack2(vh, vh);
        g_kmd[kb+o] = pack2(km, km);
        g_vmd[kb+o] = pack2(vm, vm);
    }
}

// ---------------- attention: 4 queries/thread, split-K, no-max softmax, f32x2 ----------------
#define ATTN3_SMEM (2*KQ*DP*8)   // 57344 B

__global__ void __launch_bounds__(256, 2) sam_attn4() {
    extern __shared__ u64 sm64[];
    u64* sk = sm64;            // [KQ][14]
    u64* sv = sm64 + KQ*DP;

    int sp  = blockIdx.x;      // key quarter
    int b   = blockIdx.y;
    int att = blockIdx.z;

    const u64* Kd = (att ? g_kmd : g_khd) + ((size_t)b*NPIX + (size_t)sp*KQ)*DP;
    const u64* Vd = (att ? g_vmd : g_vhd) + ((size_t)b*NPIX + (size_t)sp*KQ)*DP;
    {
        const ulonglong2* K2 = (const ulonglong2*)Kd;
        const ulonglong2* V2 = (const ulonglong2*)Vd;
        ulonglong2* sk2 = (ulonglong2*)sk;
        ulonglong2* sv2 = (ulonglong2*)sv;
        for (int i = threadIdx.x; i < KQ*DP/2; i += 256) { sk2[i] = K2[i]; sv2[i] = V2[i]; }
    }
    __syncthreads();

    const float* qb = g_qT + (size_t)b*D*NPIX;
    const float L2E = 1.44269504f;
    int q0 = threadIdx.x;
    u64 qA[D], qB[D];
    #pragma unroll
    for (int d = 0; d < D; d++) {
        qA[d] = pack2(qb[d*NPIX + q0      ]*L2E, qb[d*NPIX + q0 + 256]*L2E);
        qB[d] = pack2(qb[d*NPIX + q0 + 512]*L2E, qb[d*NPIX + q0 + 768]*L2E);
    }

    u64 accA[D], accB[D];
    #pragma unroll
    for (int d = 0; d < D; d++) { accA[d] = 0ull; accB[d] = 0ull; }
    u64 sAcc = 0ull, sBcc = 0ull;

    for (int j = 0; j < KQ; j++) {
        const ulonglong2* kr = (const ulonglong2*)(sk + j*DP);
        u64 sA0 = 0ull, sA1 = 0ull, sB0 = 0ull, sB1 = 0ull;
        #pragma unroll
        for (int p = 0; p < 6; p++) {
            ulonglong2 kk = kr[p];
            sA0 = fma2(qA[2*p],   kk.x, sA0);
            sA1 = fma2(qA[2*p+1], kk.y, sA1);
            sB0 = fma2(qB[2*p],   kk.x, sB0);
            sB1 = fma2(qB[2*p+1], kk.y, sB1);
        }
        u64 k12 = *((const u64*)kr + 12);
        sA0 = fma2(qA[12], k12, sA0);
        sB0 = fma2(qB[12], k12, sB0);
        u64 sA = add2(sA0, sA1);
        u64 sB = add2(sB0, sB1);
        float a0, a1, b0, b1;
        unpack2(sA, a0, a1); unpack2(sB, b0, b1);
        u64 pA = pack2(ex2f(a0), ex2f(a1));
        u64 pB = pack2(ex2f(b0), ex2f(b1));
        sAcc = add2(sAcc, pA);
        sBcc = add2(sBcc, pB);
        const ulonglong2* vr = (const ulonglong2*)(sv + j*DP);
        #pragma unroll
        for (int p = 0; p < 6; p++) {
            ulonglong2 vv = vr[p];
            accA[2*p]   = fma2(pA, vv.x, accA[2*p]);
            accA[2*p+1] = fma2(pA, vv.y, accA[2*p+1]);
            accB[2*p]   = fma2(pB, vv.x, accB[2*p]);
            accB[2*p+1] = fma2(pB, vv.y, accB[2*p+1]);
        }
        u64 v12 = *((const u64*)vr + 12);
        accA[12] = fma2(pA, v12, accA[12]);
        accB[12] = fma2(pB, v12, accB[12]);
    }

    float* o0 = g_part + part_idx(att, b, sp, q0);
    float* o1 = g_part + part_idx(att, b, sp, q0 + 256);
    float* o2 = g_part + part_idx(att, b, sp, q0 + 512);
    float* o3 = g_part + part_idx(att, b, sp, q0 + 768);
    #pragma unroll
    for (int d = 0; d < D; d++) {
        float lo, hi;
        unpack2(accA[d], lo, hi); o0[d] = lo; o1[d] = hi;
        unpack2(accB[d], lo, hi); o2[d] = lo; o3[d] = hi;
    }
    float lo, hi;
    unpack2(sAcc, lo, hi); o0[13] = lo; o1[13] = hi;
    unpack2(sBcc, lo, hi); o2[13] = lo; o3[13] = hi;
}

// ---------------- SAM fuse + state update ----------------
__global__ void __launch_bounds__(256) sam_post(
        const float* __restrict__ Wz, const float* __restrict__ Wm) {
    __shared__ float swz[13*26], swm[39*26];
    for (int i = threadIdx.x; i < 13*26; i += 256) swz[i] = Wz[i];
    for (int i = threadIdx.x; i < 39*26; i += 256) swm[i] = Wm[i];
    __syncthreads();
    int g = blockIdx.x*256 + threadIdx.x;
    int b = g >> 10, n = g & 1023;

    float zh[D], zm[D], hf[D], mf[D];
    float sH = 0.f, sM = 0.f;
    #pragma unroll
    for (int d = 0; d < D; d++) { zh[d] = 0.f; zm[d] = 0.f; }
    #pragma unroll
    for (int sp = 0; sp < NSPLIT; sp++) {
        const float* ph = g_part + part_idx(0, b, sp, n);
        const float* pm = g_part + part_idx(1, b, sp, n);
        #pragma unroll
        for (int d = 0; d < D; d++) { zh[d] += ph[d]; zm[d] += pm[d]; }
        sH += ph[13]; sM += pm[13];
    }
    float invH = 1.f/sH, invM = 1.f/sM;
    #pragma unroll
    for (int d = 0; d < D; d++) {
        zh[d] *= invH; zm[d] *= invM;
        size_t idx = ((size_t)b*D + d)*NPIX + n;
        hf[d] = g_htmp[idx]; mf[d] = g_m[idx];
    }
    float Z[D];
    #pragma unroll
    for (int o = 0; o < D; o++) {
        float a = 0.f;
        #pragma unroll
        for (int c = 0; c < D; c++) {
            a = fmaf(swz[o*26 + c],      zh[c], a);
            a = fmaf(swz[o*26 + 13 + c], zm[c], a);
        }
        Z[o] = a;
    }
    #pragma unroll
    for (int o = 0; o < D; o++) {
        float ao = 0.f, ag = 0.f, ai = 0.f;
        #pragma unroll
        for (int c = 0; c < D; c++) {
            ao = fmaf(swm[(     o)*26 + c], Z[c], ao); ao = fmaf(swm[(     o)*26 + 13 + c], hf[c], ao);
            ag = fmaf(swm[(13 + o)*26 + c], Z[c], ag); ag = fmaf(swm[(13 + o)*26 + 13 + c], hf[c], ag);
            ai = fmaf(swm[(26 + o)*26 + c], Z[c], ai); ai = fmaf(swm[(26 + o)*26 + 13 + c], hf[c], ai);
        }
        float mi = 1.f/(1.f + __expf(-ai));
        float mn = (1.f - mi)*mf[o] + mi*tanhf(ag);
        size_t idx = ((size_t)b*D + o)*NPIX + n;
        g_m[idx] = mn;
        g_h[idx] = mn/(1.f + __expf(-ao));
    }
}

// ---------------- final 1x1 conv + log_softmax ----------------
__global__ void __launch_bounds__(256) final_logsoftmax(
        const float* __restrict__ Wf, const float* __restrict__ bf,
        float* __restrict__ out) {
    __shared__ float sw[NCL*D], sb[NCL];
    for (int i = threadIdx.x; i < NCL*D; i += 256) sw[i] = Wf[i];
    if (threadIdx.x < NCL) sb[threadIdx.x] = bf[threadIdx.x];
    __syncthreads();
    int g = blockIdx.x*256 + threadIdx.x;
    int b = g >> 10, n = g & 1023;
    float cv[D];
    #pragma unroll
    for (int d = 0; d < D; d++) cv[d] = g_c[((size_t)b*D + d)*NPIX + n];
    float l[NCL]; float mx = -INFINITY;
    #pragma unroll
    for (int o = 0; o < NCL; o++) {
        float a = sb[o];
        #pragma unroll
        for (int d = 0; d < D; d++) a = fmaf(sw[o*13 + d], cv[d], a);
        l[o] = a; mx = fmaxf(mx, a);
    }
    float sum = 0.f;
    #pragma unroll
    for (int o = 0; o < NCL; o++) sum += __expf(l[o] - mx);
    float lse = mx + logf(sum);
    #pragma unroll
    for (int o = 0; o < NCL; o++)
        out[((size_t)b*NCL + o)*NPIX + n] = l[o] - lse;
}

// ---------------- launch ----------------
extern "C" void kernel_launch(void* const* d_in, const int* in_sizes, int n_in,
                              void* d_out, int out_size) {
    const float* x1  = (const float*)d_in[0];
    const float* Wg  = (const float*)d_in[1];
    const float* Wq  = (const float*)d_in[2];
    const float* Wkh = (const float*)d_in[3];
    const float* Wvh = (const float*)d_in[4];
    const float* Wkm = (const float*)d_in[5];
    const float* Wvm = (const float*)d_in[6];
    const float* Wz  = (const float*)d_in[7];
    const float* Wm  = (const float*)d_in[8];
    const float* Wf  = (const float*)d_in[9];
    const float* bf  = (const float*)d_in[10];
    float* out = (float*)d_out;

    cudaFuncSetAttribute(sam_attn4, cudaFuncAttributeMaxDynamicSharedMemorySize, ATTN3_SMEM);
    cudaFuncSetAttribute(conv_lstm_step, cudaFuncAttributeMaxDynamicSharedMemorySize, CONV_SMEM3);

    zero_state<<<256, 256>>>();
    pack_conv_weights<<<(CONV_WP + 255)/256, 256>>>(Wg);
    for (int t = 0; t < TSTEPS; t++) {
        conv_lstm_step<<<dim3(4, BATCH), 256, CONV_SMEM3>>>(x1, t);
        sam_proj<<<128, 256>>>(Wq, Wkh, Wvh, Wkm, Wvm);
        sam_attn4<<<dim3(NSPLIT, BATCH, 2), 256, ATTN3_SMEM>>>();
        sam_post<<<128, 256>>>(Wz, Wm);
    }
    final_logsoftmax<<<128, 256>>>(Wf, bf, out);
}

// round 4
// speedup vs baseline: 1.9926x; 1.0445x over previous
#include <cuda_runtime.h>
#include <math.h>

#define D      13
#define DP     14          // padded smem row (u64 units) -> 112B
#define NPIX   1024
#define BATCH  32
#define TSTEPS 24
#define NCL    8
#define KQ     128         // keys per attention block
#define NSPLIT 8

typedef unsigned long long u64;

__device__ __forceinline__ u64 fma2(u64 a, u64 b, u64 c) {
    u64 d; asm("fma.rn.f32x2 %0, %1, %2, %3;" : "=l"(d) : "l"(a), "l"(b), "l"(c)); return d;
}
__device__ __forceinline__ u64 add2(u64 a, u64 b) {
    u64 d; asm("add.rn.f32x2 %0, %1, %2;" : "=l"(d) : "l"(a), "l"(b)); return d;
}
__device__ __forceinline__ u64 pack2(float lo, float hi) {
    u64 d; asm("mov.b64 %0, {%1, %2};" : "=l"(d) : "f"(lo), "f"(hi)); return d;
}
__device__ __forceinline__ void unpack2(u64 v, float& lo, float& hi) {
    asm("mov.b64 {%0, %1}, %2;" : "=f"(lo), "=f"(hi) : "l"(v));
}
__device__ __forceinline__ float ex2f(float x) {
    float r; asm("ex2.approx.f32 %0, %1;" : "=f"(r) : "f"(x)); return r;
}

// ---------------- persistent state (device globals; no allocation) ----------------
__device__ float g_c   [BATCH*D*NPIX];
__device__ float g_h   [BATCH*D*NPIX];
__device__ float g_m   [BATCH*D*NPIX];
__device__ float g_htmp[BATCH*D*NPIX];
__device__ float g_q   [BATCH*D*NPIX];   // pre-scaled by log2(e), [b][d][n]
__device__ float g_kh  [BATCH*D*NPIX];
__device__ float g_vh  [BATCH*D*NPIX];
__device__ float g_km  [BATCH*D*NPIX];
__device__ float g_vm  [BATCH*D*NPIX];
__device__ float g_part[2*BATCH*NSPLIT*14*NPIX]; // [att][b][sp][d|sum][n] - plane layout

// ---------------- zero init ----------------
__global__ void zero_state() {
    int total = BATCH*D*NPIX;
    for (int i = blockIdx.x*blockDim.x + threadIdx.x; i < total; i += gridDim.x*blockDim.x) {
        g_c[i] = 0.f; g_h[i] = 0.f; g_m[i] = 0.f;
    }
}

// ---------------- conv weight pre-pack (once per launch) ----------------
#define CONV_WP (13*26*9)   // 3042 u64 per array
__device__ u64 g_wif[CONV_WP];
__device__ u64 g_wgo[CONV_WP];

__global__ void pack_conv_weights(const float* __restrict__ Wg) {
    int i = blockIdx.x*256 + threadIdx.x;
    if (i < CONV_WP) {
        int d = i / 234, r = i % 234;
        g_wif[i] = pack2(Wg[(     d)*234 + r], Wg[(13 + d)*234 + r]);
        g_wgo[i] = pack2(Wg[(26 + d)*234 + r], Wg[(39 + d)*234 + r]);
    }
}

// ---------------- ConvLSTM step + fused SAM projections ----------------
#define CONV_TILE_F  (26*10*34)
#define PROJ_W_F     (5*169)
#define CONV_SMEM4   (2*CONV_WP*8 + CONV_TILE_F*4 + PROJ_W_F*4)

__global__ void __launch_bounds__(256) conv_lstm_proj(
        const float* __restrict__ x1, int t,
        const float* __restrict__ Wq,  const float* __restrict__ Wkh,
        const float* __restrict__ Wvh, const float* __restrict__ Wkm,
        const float* __restrict__ Wvm) {
    extern __shared__ char smraw[];
    u64*   swif = (u64*)smraw;
    u64*   swgo = swif + CONV_WP;
    float* st   = (float*)(swgo + CONV_WP);
    float* spw  = st + CONV_TILE_F;          // 5*169 proj weights

    int b  = blockIdx.y;
    int y0 = blockIdx.x * 8;

    const ulonglong2* gi = (const ulonglong2*)g_wif;
    const ulonglong2* go = (const ulonglong2*)g_wgo;
    ulonglong2* si = (ulonglong2*)swif;
    ulonglong2* so = (ulonglong2*)swgo;
    for (int i = threadIdx.x; i < CONV_WP/2; i += 256) { si[i] = gi[i]; so[i] = go[i]; }
    if (threadIdx.x == 0) { swif[CONV_WP-1] = g_wif[CONV_WP-1]; swgo[CONV_WP-1] = g_wgo[CONV_WP-1]; }
    for (int i = threadIdx.x; i < 169; i += 256) {
        spw[i]     = Wq[i];  spw[169+i] = Wkh[i]; spw[338+i] = Wvh[i];
        spw[507+i] = Wkm[i]; spw[676+i] = Wvm[i];
    }
    for (int i = threadIdx.x; i < CONV_TILE_F; i += 256) {
        int ci = i / 340; int rem = i % 340; int r = rem / 34; int cc = rem % 34;
        int y = y0 + r - 1, x = cc - 1;
        float v = 0.f;
        if ((unsigned)y < 32u && (unsigned)x < 32u) {
            int n = y*32 + x;
            v = (ci < 13) ? x1[(((size_t)b*TSTEPS + t)*D + ci)*NPIX + n]
                          : g_h[((size_t)b*D + (ci-13))*NPIX + n];
        }
        st[i] = v;
    }
    __syncthreads();

    int ly = threadIdx.x >> 5;
    int lx = threadIdx.x & 31;
    int n  = (y0 + ly)*32 + lx;

    u64 aif[D], ago[D];
    #pragma unroll
    for (int d = 0; d < D; d++) { aif[d] = 0ull; ago[d] = 0ull; }

    for (int ci = 0; ci < 26; ci++) {
        const float* tb = st + (ci*10 + ly)*34 + lx;
        #pragma unroll
        for (int ky = 0; ky < 3; ky++) {
            #pragma unroll
            for (int kx = 0; kx < 3; kx++) {
                float v = tb[ky*34 + kx];
                u64 vv = pack2(v, v);
                int r = ci*9 + ky*3 + kx;
                #pragma unroll
                for (int d = 0; d < D; d++) {
                    aif[d] = fma2(swif[d*234 + r], vv, aif[d]);
                    ago[d] = fma2(swgo[d*234 + r], vv, ago[d]);
                }
            }
        }
    }

    float ht[D], mv[D];
    #pragma unroll
    for (int d = 0; d < D; d++) {
        float ai, af, ag, ao;
        unpack2(aif[d], ai, af);
        unpack2(ago[d], ag, ao);
        float ig = 1.f/(1.f + __expf(-ai));
        float fg = 1.f/(1.f + __expf(-af));
        float og = 1.f/(1.f + __expf(-ao));
        float gg = tanhf(ag);
        size_t idx = ((size_t)b*D + d)*NPIX + n;
        float cn = fg*g_c[idx] + ig*gg;
        g_c[idx] = cn;
        float htv = og*tanhf(cn);
        ht[d] = htv;
        g_htmp[idx] = htv;
        mv[d] = g_m[idx];
    }

    // fused projections (coalesced plane writes)
    const float L2E = 1.44269504f;
    size_t pb = (size_t)b*D*NPIX + n;
    #pragma unroll
    for (int o = 0; o < D; o++) {
        float q = 0.f, kh = 0.f, vh = 0.f, km = 0.f, vm = 0.f;
        #pragma unroll
        for (int d = 0; d < D; d++) {
            q  = fmaf(spw[      o*13 + d], ht[d], q);
            kh = fmaf(spw[169 + o*13 + d], ht[d], kh);
            vh = fmaf(spw[338 + o*13 + d], ht[d], vh);
            km = fmaf(spw[507 + o*13 + d], mv[d], km);
            vm = fmaf(spw[676 + o*13 + d], mv[d], vm);
        }
        g_q [pb + (size_t)o*NPIX] = q*L2E;
        g_kh[pb + (size_t)o*NPIX] = kh;
        g_vh[pb + (size_t)o*NPIX] = vh;
        g_km[pb + (size_t)o*NPIX] = km;
        g_vm[pb + (size_t)o*NPIX] = vm;
    }
}

// ---------------- attention: 2 queries/thread, split-K, plane-coalesced I/O ----------------
#define ATTN4_SMEM (2*KQ*DP*8)   // 28672 B

__global__ void __launch_bounds__(256, 3) sam_attn() {
    extern __shared__ u64 sm64[];
    u64* sk = sm64;            // [KQ][14] duplicated (k,k)
    u64* sv = sm64 + KQ*DP;

    int sp  = blockIdx.x;          // key slice
    int b   = blockIdx.y;
    int att = blockIdx.z & 1;
    int qh  = blockIdx.z >> 1;     // query half

    const float* Kp = (att ? g_km : g_kh) + (size_t)b*D*NPIX + sp*KQ;
    const float* Vp = (att ? g_vm : g_vh) + (size_t)b*D*NPIX + sp*KQ;
    for (int i = threadIdx.x; i < D*KQ; i += 256) {
        int d = i >> 7, j = i & (KQ-1);
        float kv = Kp[(size_t)d*NPIX + j];
        float vv = Vp[(size_t)d*NPIX + j];
        sk[j*DP + d] = pack2(kv, kv);
        sv[j*DP + d] = pack2(vv, vv);
    }
    __syncthreads();

    int q0 = qh*512 + threadIdx.x;       // and q0+256
    const float* qb = g_q + (size_t)b*D*NPIX;
    u64 q2[D];
    #pragma unroll
    for (int d = 0; d < D; d++) q2[d] = pack2(qb[(size_t)d*NPIX + q0], qb[(size_t)d*NPIX + q0 + 256]);

    u64 acc[D];
    #pragma unroll
    for (int d = 0; d < D; d++) acc[d] = 0ull;
    u64 sAcc = 0ull;

    for (int j = 0; j < KQ; j++) {
        const ulonglong2* kr = (const ulonglong2*)(sk + j*DP);
        ulonglong2 k01 = kr[0], k23 = kr[1], k45 = kr[2];
        u64 s0 = fma2(q2[0], k01.x, 0ull);
        u64 s1 = fma2(q2[1], k01.y, 0ull);
        u64 s2 = fma2(q2[2], k23.x, 0ull);
        u64 s3 = fma2(q2[3], k23.y, 0ull);
        s0 = fma2(q2[4], k45.x, s0);
        s1 = fma2(q2[5], k45.y, s1);
        ulonglong2 k67 = kr[3], k89 = kr[4], kab = kr[5];
        s2 = fma2(q2[6],  k67.x, s2);
        s3 = fma2(q2[7],  k67.y, s3);
        s0 = fma2(q2[8],  k89.x, s0);
        s1 = fma2(q2[9],  k89.y, s1);
        s2 = fma2(q2[10], kab.x, s2);
        s3 = fma2(q2[11], kab.y, s3);
        u64 k12 = *((const u64*)kr + 12);
        s0 = fma2(q2[12], k12, s0);
        s0 = add2(s0, s1);
        s2 = add2(s2, s3);
        s0 = add2(s0, s2);
        float e0, e1;
        unpack2(s0, e0, e1);
        u64 p = pack2(ex2f(e0), ex2f(e1));   // scores already in log2 units
        sAcc = add2(sAcc, p);
        const ulonglong2* vr = (const ulonglong2*)(sv + j*DP);
        #pragma unroll
        for (int pp = 0; pp < 6; pp++) {
            ulonglong2 vv = vr[pp];
            acc[2*pp]   = fma2(p, vv.x, acc[2*pp]);
            acc[2*pp+1] = fma2(p, vv.y, acc[2*pp+1]);
        }
        u64 v12 = *((const u64*)vr + 12);
        acc[12] = fma2(p, v12, acc[12]);
    }

    float* ob = g_part + ((((size_t)att*BATCH + b)*NSPLIT + sp)*14)*NPIX;
    #pragma unroll
    for (int d = 0; d < D; d++) {
        float lo, hi; unpack2(acc[d], lo, hi);
        ob[(size_t)d*NPIX + q0]       = lo;
        ob[(size_t)d*NPIX + q0 + 256] = hi;
    }
    float lo, hi; unpack2(sAcc, lo, hi);
    ob[(size_t)13*NPIX + q0]       = lo;
    ob[(size_t)13*NPIX + q0 + 256] = hi;
}

// ---------------- SAM fuse + state update ----------------
__global__ void __launch_bounds__(256) sam_post(
        const float* __restrict__ Wz, const float* __restrict__ Wm) {
    __shared__ float swz[13*26], swm[39*26];
    for (int i = threadIdx.x; i < 13*26; i += 256) swz[i] = Wz[i];
    for (int i = threadIdx.x; i < 39*26; i += 256) swm[i] = Wm[i];
    __syncthreads();
    int g = blockIdx.x*256 + threadIdx.x;
    int b = g >> 10, n = g & 1023;

    float zh[D], zm[D], hf[D], mf[D];
    float sH = 0.f, sM = 0.f;
    #pragma unroll
    for (int d = 0; d < D; d++) { zh[d] = 0.f; zm[d] = 0.f; }
    const float* baseH = g_part + ((size_t)b*NSPLIT)*14*NPIX + n;
    const float* baseM = g_part + (((size_t)BATCH + b)*NSPLIT)*14*NPIX + n;
    #pragma unroll
    for (int sp = 0; sp < NSPLIT; sp++) {
        const float* ph = baseH + (size_t)sp*14*NPIX;
        const float* pm = baseM + (size_t)sp*14*NPIX;
        #pragma unroll
        for (int d = 0; d < D; d++) { zh[d] += ph[(size_t)d*NPIX]; zm[d] += pm[(size_t)d*NPIX]; }
        sH += ph[(size_t)13*NPIX]; sM += pm[(size_t)13*NPIX];
    }
    float invH = 1.f/sH, invM = 1.f/sM;
    #pragma unroll
    for (int d = 0; d < D; d++) {
        zh[d] *= invH; zm[d] *= invM;
        size_t idx = ((size_t)b*D + d)*NPIX + n;
        hf[d] = g_htmp[idx]; mf[d] = g_m[idx];
    }
    float Z[D];
    #pragma unroll
    for (int o = 0; o < D; o++) {
        float a = 0.f;
        #pragma unroll
        for (int c = 0; c < D; c++) {
            a = fmaf(swz[o*26 + c],      zh[c], a);
            a = fmaf(swz[o*26 + 13 + c], zm[c], a);
        }
        Z[o] = a;
    }
    #pragma unroll
    for (int o = 0; o < D; o++) {
        float ao = 0.f, ag = 0.f, ai = 0.f;
        #pragma unroll
        for (int c = 0; c < D; c++) {
            ao = fmaf(swm[(     o)*26 + c], Z[c], ao); ao = fmaf(swm[(     o)*26 + 13 + c], hf[c], ao);
            ag = fmaf(swm[(13 + o)*26 + c], Z[c], ag); ag = fmaf(swm[(13 + o)*26 + 13 + c], hf[c], ag);
            ai = fmaf(swm[(26 + o)*26 + c], Z[c], ai); ai = fmaf(swm[(26 + o)*26 + 13 + c], hf[c], ai);
        }
        float mi = 1.f/(1.f + __expf(-ai));
        float mn = (1.f - mi)*mf[o] + mi*tanhf(ag);
        size_t idx = ((size_t)b*D + o)*NPIX + n;
        g_m[idx] = mn;
        g_h[idx] = mn/(1.f + __expf(-ao));
    }
}

// ---------------- final 1x1 conv + log_softmax ----------------
__global__ void __launch_bounds__(256) final_logsoftmax(
        const float* __restrict__ Wf, const float* __restrict__ bf,
        float* __restrict__ out) {
    __shared__ float sw[NCL*D], sb[NCL];
    for (int i = threadIdx.x; i < NCL*D; i += 256) sw[i] = Wf[i];
    if (threadIdx.x < NCL) sb[threadIdx.x] = bf[threadIdx.x];
    __syncthreads();
    int g = blockIdx.x*256 + threadIdx.x;
    int b = g >> 10, n = g & 1023;
    float cv[D];
    #pragma unroll
    for (int d = 0; d < D; d++) cv[d] = g_c[((size_t)b*D + d)*NPIX + n];
    float l[NCL]; float mx = -INFINITY;
    #pragma unroll
    for (int o = 0; o < NCL; o++) {
        float a = sb[o];
        #pragma unroll
        for (int d = 0; d < D; d++) a = fmaf(sw[o*13 + d], cv[d], a);
        l[o] = a; mx = fmaxf(mx, a);
    }
    float sum = 0.f;
    #pragma unroll
    for (int o = 0; o < NCL; o++) sum += __expf(l[o] - mx);
    float lse = mx + logf(sum);
    #pragma unroll
    for (int o = 0; o < NCL; o++)
        out[((size_t)b*NCL + o)*NPIX + n] = l[o] - lse;
}

// ---------------- launch ----------------
extern "C" void kernel_launch(void* const* d_in, const int* in_sizes, int n_in,
                              void* d_out, int out_size) {
    const float* x1  = (const float*)d_in[0];
    const float* Wg  = (const float*)d_in[1];
    const float* Wq  = (const float*)d_in[2];
    const float* Wkh = (const float*)d_in[3];
    const float* Wvh = (const float*)d_in[4];
    const float* Wkm = (const float*)d_in[5];
    const float* Wvm = (const float*)d_in[6];
    const float* Wz  = (const float*)d_in[7];
    const float* Wm  = (const float*)d_in[8];
    const float* Wf  = (const float*)d_in[9];
    const float* bf  = (const float*)d_in[10];
    float* out = (float*)d_out;

    cudaFuncSetAttribute(sam_attn, cudaFuncAttributeMaxDynamicSharedMemorySize, ATTN4_SMEM);
    cudaFuncSetAttribute(conv_lstm_proj, cudaFuncAttributeMaxDynamicSharedMemorySize, CONV_SMEM4);

    zero_state<<<256, 256>>>();
    pack_conv_weights<<<(CONV_WP + 255)/256, 256>>>(Wg);
    for (int t = 0; t < TSTEPS; t++) {
        conv_lstm_proj<<<dim3(4, BATCH), 256, CONV_SMEM4>>>(x1, t, Wq, Wkh, Wvh, Wkm, Wvm);
        sam_attn<<<dim3(NSPLIT, BATCH, 4), 256, ATTN4_SMEM>>>();
        sam_post<<<128, 256>>>(Wz, Wm);
    }
    final_logsoftmax<<<128, 256>>>(Wf, bf, out);
}

// round 5
// speedup vs baseline: 2.5468x; 1.2781x over previous
#include <cuda_runtime.h>
#include <math.h>

#define D      13
#define NPIX   1024
#define BATCH  32
#define TSTEPS 24
#define NCL    8
#define KQ     256         // keys per attention block
#define NSPLIT 4

typedef unsigned long long u64;

__device__ __forceinline__ u64 fma2(u64 a, u64 b, u64 c) {
    u64 d; asm("fma.rn.f32x2 %0, %1, %2, %3;" : "=l"(d) : "l"(a), "l"(b), "l"(c)); return d;
}
__device__ __forceinline__ u64 add2(u64 a, u64 b) {
    u64 d; asm("add.rn.f32x2 %0, %1, %2;" : "=l"(d) : "l"(a), "l"(b)); return d;
}
__device__ __forceinline__ u64 pack2(float lo, float hi) {
    u64 d; asm("mov.b64 %0, {%1, %2};" : "=l"(d) : "f"(lo), "f"(hi)); return d;
}
__device__ __forceinline__ void unpack2(u64 v, float& lo, float& hi) {
    asm("mov.b64 {%0, %1}, %2;" : "=f"(lo), "=f"(hi) : "l"(v));
}
__device__ __forceinline__ float ex2f(float x) {
    float r; asm("ex2.approx.f32 %0, %1;" : "=f"(r) : "f"(x)); return r;
}

// ---------------- persistent state ----------------
__device__ float g_c   [BATCH*D*NPIX];
__device__ float g_h   [BATCH*D*NPIX];
__device__ float g_m   [BATCH*D*NPIX];
__device__ float g_htmp[BATCH*D*NPIX];
__device__ float g_q   [BATCH*D*NPIX];   // pre-scaled by log2(e), [b][d][n]
__device__ float g_kh  [BATCH*D*NPIX];
__device__ float g_vh  [BATCH*D*NPIX];
__device__ float g_km  [BATCH*D*NPIX];
__device__ float g_vm  [BATCH*D*NPIX];
__device__ float g_part[2*BATCH*NSPLIT*14*NPIX]; // [att][b][sp][d|sum][n]

__global__ void zero_state() {
    int total = BATCH*D*NPIX;
    for (int i = blockIdx.x*blockDim.x + threadIdx.x; i < total; i += gridDim.x*blockDim.x) {
        g_c[i] = 0.f; g_h[i] = 0.f; g_m[i] = 0.f;
    }
}

// ---------------- conv weight pre-pack ----------------
#define CONV_WP (13*26*9)
__device__ u64 g_wif[CONV_WP];
__device__ u64 g_wgo[CONV_WP];

__global__ void pack_conv_weights(const float* __restrict__ Wg) {
    int i = blockIdx.x*256 + threadIdx.x;
    if (i < CONV_WP) {
        int d = i / 234, r = i % 234;
        g_wif[i] = pack2(Wg[(     d)*234 + r], Wg[(13 + d)*234 + r]);
        g_wgo[i] = pack2(Wg[(26 + d)*234 + r], Wg[(39 + d)*234 + r]);
    }
}

// ---------------- ConvLSTM step + fused SAM projections ----------------
#define CONV_TILE_F  (26*10*34)
#define PROJ_W_F     (5*169)
#define CONV_SMEM4   (2*CONV_WP*8 + CONV_TILE_F*4 + PROJ_W_F*4)

__global__ void __launch_bounds__(256) conv_lstm_proj(
        const float* __restrict__ x1, int t,
        const float* __restrict__ Wq,  const float* __restrict__ Wkh,
        const float* __restrict__ Wvh, const float* __restrict__ Wkm,
        const float* __restrict__ Wvm) {
    extern __shared__ char smraw[];
    u64*   swif = (u64*)smraw;
    u64*   swgo = swif + CONV_WP;
    float* st   = (float*)(swgo + CONV_WP);
    float* spw  = st + CONV_TILE_F;

    int b  = blockIdx.y;
    int y0 = blockIdx.x * 8;

    const ulonglong2* gi = (const ulonglong2*)g_wif;
    const ulonglong2* go = (const ulonglong2*)g_wgo;
    ulonglong2* si = (ulonglong2*)swif;
    ulonglong2* so = (ulonglong2*)swgo;
    for (int i = threadIdx.x; i < CONV_WP/2; i += 256) { si[i] = gi[i]; so[i] = go[i]; }
    if (threadIdx.x == 0) { swif[CONV_WP-1] = g_wif[CONV_WP-1]; swgo[CONV_WP-1] = g_wgo[CONV_WP-1]; }
    for (int i = threadIdx.x; i < 169; i += 256) {
        spw[i]     = Wq[i];  spw[169+i] = Wkh[i]; spw[338+i] = Wvh[i];
        spw[507+i] = Wkm[i]; spw[676+i] = Wvm[i];
    }
    for (int i = threadIdx.x; i < CONV_TILE_F; i += 256) {
        int ci = i / 340; int rem = i % 340; int r = rem / 34; int cc = rem % 34;
        int y = y0 + r - 1, x = cc - 1;
        float v = 0.f;
        if ((unsigned)y < 32u && (unsigned)x < 32u) {
            int n = y*32 + x;
            v = (ci < 13) ? x1[(((size_t)b*TSTEPS + t)*D + ci)*NPIX + n]
                          : g_h[((size_t)b*D + (ci-13))*NPIX + n];
        }
        st[i] = v;
    }
    __syncthreads();

    int ly = threadIdx.x >> 5;
    int lx = threadIdx.x & 31;
    int n  = (y0 + ly)*32 + lx;

    u64 aif[D], ago[D];
    #pragma unroll
    for (int d = 0; d < D; d++) { aif[d] = 0ull; ago[d] = 0ull; }

    for (int ci = 0; ci < 26; ci++) {
        const float* tb = st + (ci*10 + ly)*34 + lx;
        #pragma unroll
        for (int ky = 0; ky < 3; ky++) {
            #pragma unroll
            for (int kx = 0; kx < 3; kx++) {
                float v = tb[ky*34 + kx];
                u64 vv = pack2(v, v);
                int r = ci*9 + ky*3 + kx;
                #pragma unroll
                for (int d = 0; d < D; d++) {
                    aif[d] = fma2(swif[d*234 + r], vv, aif[d]);
                    ago[d] = fma2(swgo[d*234 + r], vv, ago[d]);
                }
            }
        }
    }

    float ht[D], mv[D];
    #pragma unroll
    for (int d = 0; d < D; d++) {
        float ai, af, ag, ao;
        unpack2(aif[d], ai, af);
        unpack2(ago[d], ag, ao);
        float ig = 1.f/(1.f + __expf(-ai));
        float fg = 1.f/(1.f + __expf(-af));
        float og = 1.f/(1.f + __expf(-ao));
        float gg = tanhf(ag);
        size_t idx = ((size_t)b*D + d)*NPIX + n;
        float cn = fg*g_c[idx] + ig*gg;
        g_c[idx] = cn;
        float htv = og*tanhf(cn);
        ht[d] = htv;
        g_htmp[idx] = htv;
        mv[d] = g_m[idx];
    }

    const float L2E = 1.44269504f;
    size_t pb = (size_t)b*D*NPIX + n;
    #pragma unroll
    for (int o = 0; o < D; o++) {
        float q = 0.f, kh = 0.f, vh = 0.f, km = 0.f, vm = 0.f;
        #pragma unroll
        for (int d = 0; d < D; d++) {
            q  = fmaf(spw[      o*13 + d], ht[d], q);
            kh = fmaf(spw[169 + o*13 + d], ht[d], kh);
            vh = fmaf(spw[338 + o*13 + d], ht[d], vh);
            km = fmaf(spw[507 + o*13 + d], mv[d], km);
            vm = fmaf(spw[676 + o*13 + d], mv[d], vm);
        }
        g_q [pb + (size_t)o*NPIX] = q*L2E;
        g_kh[pb + (size_t)o*NPIX] = kh;
        g_vh[pb + (size_t)o*NPIX] = vh;
        g_km[pb + (size_t)o*NPIX] = km;
        g_vm[pb + (size_t)o*NPIX] = vm;
    }
}

// ---------------- attention: plane smem, key-packed f32x2, 2 queries/thread ----------------
#define ATTN5_SMEM (2*D*KQ*4)   // 26624 B

__global__ void __launch_bounds__(256, 2) sam_attn() {
    extern __shared__ float smf[];
    float* sk = smf;            // [13][KQ] plane
    float* sv = smf + D*KQ;

    int sp  = blockIdx.x;
    int b   = blockIdx.y;
    int att = blockIdx.z & 1;
    int qh  = blockIdx.z >> 1;

    const float* Kp = (att ? g_km : g_kh) + (size_t)b*D*NPIX + sp*KQ;
    const float* Vp = (att ? g_vm : g_vh) + (size_t)b*D*NPIX + sp*KQ;
    // coalesced float4 cooperative load: 13 rows x 64 float4 per plane
    {
        float4* sk4 = (float4*)sk;
        float4* sv4 = (float4*)sv;
        for (int i = threadIdx.x; i < D*(KQ/4); i += 256) {
            int d = i >> 6, c = i & 63;
            sk4[d*(KQ/4) + c] = *(const float4*)(Kp + (size_t)d*NPIX + c*4);
            sv4[d*(KQ/4) + c] = *(const float4*)(Vp + (size_t)d*NPIX + c*4);
        }
    }
    __syncthreads();

    int q0 = qh*512 + threadIdx.x;   // and q0+256
    const float* qb = g_q + (size_t)b*D*NPIX;
    float qa[D], qc[D];
    #pragma unroll
    for (int d = 0; d < D; d++) {
        qa[d] = qb[(size_t)d*NPIX + q0];
        qc[d] = qb[(size_t)d*NPIX + q0 + 256];
    }

    u64 acc0[D], acc1[D];
    #pragma unroll
    for (int d = 0; d < D; d++) { acc0[d] = 0ull; acc1[d] = 0ull; }
    u64 sum0 = 0ull, sum1 = 0ull;

    for (int j = 0; j < KQ; j += 4) {
        // scores: key-packed pairs (j,j+1) and (j+2,j+3) for each query
        u64 sA0 = 0ull, sB0 = 0ull, sA1 = 0ull, sB1 = 0ull;
        #pragma unroll
        for (int d = 0; d < D; d++) {
            const ulonglong2 kk = *(const ulonglong2*)(sk + d*KQ + j);
            u64 qd0 = pack2(qa[d], qa[d]);
            u64 qd1 = pack2(qc[d], qc[d]);
            sA0 = fma2(qd0, kk.x, sA0);
            sB0 = fma2(qd0, kk.y, sB0);
            sA1 = fma2(qd1, kk.x, sA1);
            sB1 = fma2(qd1, kk.y, sB1);
        }
        float e0, e1;
        unpack2(sA0, e0, e1); u64 pA0 = pack2(ex2f(e0), ex2f(e1));
        unpack2(sB0, e0, e1); u64 pB0 = pack2(ex2f(e0), ex2f(e1));
        unpack2(sA1, e0, e1); u64 pA1 = pack2(ex2f(e0), ex2f(e1));
        unpack2(sB1, e0, e1); u64 pB1 = pack2(ex2f(e0), ex2f(e1));
        sum0 = add2(sum0, add2(pA0, pB0));
        sum1 = add2(sum1, add2(pA1, pB1));
        #pragma unroll
        for (int d = 0; d < D; d++) {
            const ulonglong2 vv = *(const ulonglong2*)(sv + d*KQ + j);
            acc0[d] = fma2(pA0, vv.x, acc0[d]);
            acc0[d] = fma2(pB0, vv.y, acc0[d]);
            acc1[d] = fma2(pA1, vv.x, acc1[d]);
            acc1[d] = fma2(pB1, vv.y, acc1[d]);
        }
    }

    float* ob = g_part + ((((size_t)att*BATCH + b)*NSPLIT + sp)*14)*NPIX;
    #pragma unroll
    for (int d = 0; d < D; d++) {
        float lo, hi;
        unpack2(acc0[d], lo, hi);
        ob[(size_t)d*NPIX + q0] = lo + hi;
        unpack2(acc1[d], lo, hi);
        ob[(size_t)d*NPIX + q0 + 256] = lo + hi;
    }
    float lo, hi;
    unpack2(sum0, lo, hi); ob[(size_t)13*NPIX + q0]       = lo + hi;
    unpack2(sum1, lo, hi); ob[(size_t)13*NPIX + q0 + 256] = lo + hi;
}

// ---------------- SAM fuse + state update ----------------
__global__ void __launch_bounds__(256) sam_post(
        const float* __restrict__ Wz, const float* __restrict__ Wm) {
    __shared__ float swz[13*26], swm[39*26];
    for (int i = threadIdx.x; i < 13*26; i += 256) swz[i] = Wz[i];
    for (int i = threadIdx.x; i < 39*26; i += 256) swm[i] = Wm[i];
    __syncthreads();
    int g = blockIdx.x*256 + threadIdx.x;
    int b = g >> 10, n = g & 1023;

    float zh[D], zm[D], hf[D], mf[D];
    float sH = 0.f, sM = 0.f;
    #pragma unroll
    for (int d = 0; d < D; d++) { zh[d] = 0.f; zm[d] = 0.f; }
    const float* baseH = g_part + ((size_t)b*NSPLIT)*14*NPIX + n;
    const float* baseM = g_part + (((size_t)BATCH + b)*NSPLIT)*14*NPIX + n;
    #pragma unroll
    for (int sp = 0; sp < NSPLIT; sp++) {
        const float* ph = baseH + (size_t)sp*14*NPIX;
        const float* pm = baseM + (size_t)sp*14*NPIX;
        #pragma unroll
        for (int d = 0; d < D; d++) { zh[d] += ph[(size_t)d*NPIX]; zm[d] += pm[(size_t)d*NPIX]; }
        sH += ph[(size_t)13*NPIX]; sM += pm[(size_t)13*NPIX];
    }
    float invH = 1.f/sH, invM = 1.f/sM;
    #pragma unroll
    for (int d = 0; d < D; d++) {
        zh[d] *= invH; zm[d] *= invM;
        size_t idx = ((size_t)b*D + d)*NPIX + n;
        hf[d] = g_htmp[idx]; mf[d] = g_m[idx];
    }
    float Z[D];
    #pragma unroll
    for (int o = 0; o < D; o++) {
        float a = 0.f;
        #pragma unroll
        for (int c = 0; c < D; c++) {
            a = fmaf(swz[o*26 + c],      zh[c], a);
            a = fmaf(swz[o*26 + 13 + c], zm[c], a);
        }
        Z[o] = a;
    }
    #pragma unroll
    for (int o = 0; o < D; o++) {
        float ao = 0.f, ag = 0.f, ai = 0.f;
        #pragma unroll
        for (int c = 0; c < D; c++) {
            ao = fmaf(swm[(     o)*26 + c], Z[c], ao); ao = fmaf(swm[(     o)*26 + 13 + c], hf[c], ao);
            ag = fmaf(swm[(13 + o)*26 + c], Z[c], ag); ag = fmaf(swm[(13 + o)*26 + 13 + c], hf[c], ag);
            ai = fmaf(swm[(26 + o)*26 + c], Z[c], ai); ai = fmaf(swm[(26 + o)*26 + 13 + c], hf[c], ai);
        }
        float mi = 1.f/(1.f + __expf(-ai));
        float mn = (1.f - mi)*mf[o] + mi*tanhf(ag);
        size_t idx = ((size_t)b*D + o)*NPIX + n;
        g_m[idx] = mn;
        g_h[idx] = mn/(1.f + __expf(-ao));
    }
}

// ---------------- final 1x1 conv + log_softmax ----------------
__global__ void __launch_bounds__(256) final_logsoftmax(
        const float* __restrict__ Wf, const float* __restrict__ bf,
        float* __restrict__ out) {
    __shared__ float sw[NCL*D], sb[NCL];
    for (int i = threadIdx.x; i < NCL*D; i += 256) sw[i] = Wf[i];
    if (threadIdx.x < NCL) sb[threadIdx.x] = bf[threadIdx.x];
    __syncthreads();
    int g = blockIdx.x*256 + threadIdx.x;
    int b = g >> 10, n = g & 1023;
    float cv[D];
    #pragma unroll
    for (int d = 0; d < D; d++) cv[d] = g_c[((size_t)b*D + d)*NPIX + n];
    float l[NCL]; float mx = -INFINITY;
    #pragma unroll
    for (int o = 0; o < NCL; o++) {
        float a = sb[o];
        #pragma unroll
        for (int d = 0; d < D; d++) a = fmaf(sw[o*13 + d], cv[d], a);
        l[o] = a; mx = fmaxf(mx, a);
    }
    float sum = 0.f;
    #pragma unroll
    for (int o = 0; o < NCL; o++) sum += __expf(l[o] - mx);
    float lse = mx + logf(sum);
    #pragma unroll
    for (int o = 0; o < NCL; o++)
        out[((size_t)b*NCL + o)*NPIX + n] = l[o] - lse;
}

// ---------------- launch ----------------
extern "C" void kernel_launch(void* const* d_in, const int* in_sizes, int n_in,
                              void* d_out, int out_size) {
    const float* x1  = (const float*)d_in[0];
    const float* Wg  = (const float*)d_in[1];
    const float* Wq  = (const float*)d_in[2];
    const float* Wkh = (const float*)d_in[3];
    const float* Wvh = (const float*)d_in[4];
    const float* Wkm = (const float*)d_in[5];
    const float* Wvm = (const float*)d_in[6];
    const float* Wz  = (const float*)d_in[7];
    const float* Wm  = (const float*)d_in[8];
    const float* Wf  = (const float*)d_in[9];
    const float* bf  = (const float*)d_in[10];
    float* out = (float*)d_out;

    cudaFuncSetAttribute(sam_attn, cudaFuncAttributeMaxDynamicSharedMemorySize, ATTN5_SMEM);
    cudaFuncSetAttribute(conv_lstm_proj, cudaFuncAttributeMaxDynamicSharedMemorySize, CONV_SMEM4);

    zero_state<<<256, 256>>>();
    pack_conv_weights<<<(CONV_WP + 255)/256, 256>>>(Wg);
    for (int t = 0; t < TSTEPS; t++) {
        conv_lstm_proj<<<dim3(4, BATCH), 256, CONV_SMEM4>>>(x1, t, Wq, Wkh, Wvh, Wkm, Wvm);
        sam_attn<<<dim3(NSPLIT, BATCH, 4), 256, ATTN5_SMEM>>>();
        sam_post<<<128, 256>>>(Wz, Wm);
    }
    final_logsoftmax<<<128, 256>>>(Wf, bf, out);
}